// round 5
// baseline (speedup 1.0000x reference)
#include <cuda_runtime.h>

#define S_DIM 16
#define M_DIM 768
#define N_DIM 1024
#define ROWS_PER_BLK 4
#define STAGE_ROWS 6              // ybase-1 .. ybase+4
#define LPAD 68                   // even; covers x0 >= -65
#define RPAD 4
#define RSTRIDE (LPAD + N_DIM + RPAD)   // 1096 floats (even), 4384 B
#define B_OFF (STAGE_ROWS * RSTRIDE)    // copy-B base offset (16B-aligned)
#define INVALID_VAL 100.0f

__global__ __launch_bounds__(256) void lr_distance_kernel(
    const float* __restrict__ lr,
    const float* __restrict__ rl,
    float* __restrict__ out)
{
    // Copy A: padded rows.  Copy B: padded rows shifted left by 1 (B[i] = row[i+1]).
    __shared__ __align__(16) float sm[2 * STAGE_ROWS * RSTRIDE];   // 52608 B

    const int tid   = threadIdx.x;
    const int bid   = blockIdx.x;
    const int s     = bid / (M_DIM / ROWS_PER_BLK);
    const int grp   = bid % (M_DIM / ROWS_PER_BLK);
    const int ybase = grp * ROWS_PER_BLK;
    const int g0    = ybase - 1;

    const float* __restrict__ img = rl + s * (M_DIM * N_DIM);

    // Zero pads. A pads: [0,LPAD) and [LPAD+N, RSTRIDE) -> 72/row.
    // B pads: [0,LPAD-1) and [LPAD+N-1, RSTRIDE) -> 72/row.
    // (B[LPAD-1]=row[0] and A right pads are disjoint from staging writes -> no race.)
    for (int v = tid; v < STAGE_ROWS * (LPAD + RPAD); v += 256) {
        int r = v / (LPAD + RPAD);
        int p = v % (LPAD + RPAD);
        int ia = (p < LPAD)     ? p : (LPAD + N_DIM     + (p - LPAD));
        int ib = (p < LPAD - 1) ? p : (LPAD + N_DIM - 1 + (p - (LPAD - 1)));
        sm[r * RSTRIDE + ia]         = 0.0f;
        sm[B_OFF + r * RSTRIDE + ib] = 0.0f;
    }

    // Stage 6 rows into both copies (zero rows outside [0,M)).
    #pragma unroll
    for (int v = tid; v < STAGE_ROWS * (N_DIM / 4); v += 256) {
        int r = v >> 8;
        int c = v & 255;
        int g = g0 + r;
        float4 val = make_float4(0.0f, 0.0f, 0.0f, 0.0f);
        if (g >= 0 && g < M_DIM)
            val = *reinterpret_cast<const float4*>(img + g * N_DIM + c * 4);

        float* a = sm + r * RSTRIDE + LPAD + c * 4;
        *reinterpret_cast<float4*>(a) = val;

        // B[LPAD-1+4c .. LPAD+2+4c] = row[4c .. 4c+3]
        float* b = sm + B_OFF + r * RSTRIDE + LPAD - 1 + c * 4;
        b[0] = val.x;
        *reinterpret_cast<float2*>(b + 1) = make_float2(val.y, val.z);  // even idx, 8B aligned
        b[3] = val.w;
    }
    __syncthreads();

    const int   xs    = tid * 4;
    const float xlb   = (float)xs;
    const int   sbase = s * (M_DIM * N_DIM);

    #pragma unroll
    for (int r = 0; r < ROWS_PER_BLK; r++) {
        const int y = ybase + r;

        float yl  = 2.0f * (float)y / (float)(M_DIM - 1) - 1.0f;
        float iy  = ((yl + 1.0f) * (float)M_DIM - 1.0f) * 0.5f;
        float y0f = floorf(iy);
        float wy1 = iy - y0f;
        int   r0  = (int)y0f - g0;                // in [0,4]
        const float* __restrict__ pa = sm + r0 * RSTRIDE;
        const float* __restrict__ pb = sm + B_OFF + r0 * RSTRIDE;

        float4 dv = *reinterpret_cast<const float4*>(lr + sbase + y * N_DIM + xs);
        float dd[4] = {dv.x, dv.y, dv.z, dv.w};
        float res[4];

        #pragma unroll
        for (int j = 0; j < 4; j++) {
            float d  = dd[j];
            float xr = (xlb + (float)j) - d;

            float xr_normed = 2.0f * xr / (float)(N_DIM - 1) - 1.0f;
            float ix = ((xr_normed + 1.0f) * (float)N_DIM - 1.0f) * 0.5f;

            float x0f = floorf(ix);
            float wx1 = ix - x0f;
            int   idx = (int)x0f + LPAD;          // provably in [3, 1091]
            int   e   = idx & ~1;
            const float* base = (idx & 1) ? pb : pa;

            float2 top = *reinterpret_cast<const float2*>(base + e);            // row y0: (v00,v01)
            float2 bot = *reinterpret_cast<const float2*>(base + e + RSTRIDE);  // row y0+1

            float t = fmaf(wx1, top.y - top.x, top.x);
            float b = fmaf(wx1, bot.y - bot.x, bot.x);
            float warped = fmaf(wy1, b - t, t);

            float dist = fabsf(d + warped);
            bool invalid = (xr < 0.0f) || (xr >= (float)N_DIM);
            res[j] = invalid ? INVALID_VAL : dist;
        }

        *reinterpret_cast<float4*>(out + sbase + y * N_DIM + xs) =
            make_float4(res[0], res[1], res[2], res[3]);
    }
}

extern "C" void kernel_launch(void* const* d_in, const int* in_sizes, int n_in,
                              void* d_out, int out_size)
{
    const float* lr = (const float*)d_in[0];
    const float* rl = (const float*)d_in[1];
    float* out = (float*)d_out;

    int blocks = S_DIM * (M_DIM / ROWS_PER_BLK);   // 3072
    lr_distance_kernel<<<blocks, 256>>>(lr, rl, out);
}

// round 6
// speedup vs baseline: 1.3692x; 1.3692x over previous
#include <cuda_runtime.h>
#include <cstdint>

#define S_DIM 16
#define M_DIM 768
#define N_DIM 1024
#define ROWS_PER_BLK 4
#define STAGE_ROWS 6              // ybase-1 .. ybase+4
#define LPAD 68                   // covers x0 >= -65; LPAD*4 = 272 B (16B multiple)
#define RPAD 4
#define RSTRIDE (LPAD + N_DIM + RPAD)   // 1096 floats = 4384 B (16B multiple)
#define ROW_BYTES (N_DIM * 4)     // 4096
#define INVALID_VAL 100.0f

__device__ __forceinline__ uint32_t smem_u32(const void* p) {
    return (uint32_t)__cvta_generic_to_shared(p);
}

__global__ __launch_bounds__(256) void lr_distance_kernel(
    const float* __restrict__ lr,
    const float* __restrict__ rl,
    float* __restrict__ out)
{
    __shared__ __align__(16) float sm[STAGE_ROWS * RSTRIDE];   // 26304 B
    __shared__ __align__(8)  uint64_t mbar;

    const int tid   = threadIdx.x;
    const int bid   = blockIdx.x;
    const int s     = bid / (M_DIM / ROWS_PER_BLK);
    const int grp   = bid % (M_DIM / ROWS_PER_BLK);
    const int ybase = grp * ROWS_PER_BLK;
    const int g0    = ybase - 1;                 // first staged global row

    const float* __restrict__ img = rl + s * (M_DIM * N_DIM);
    const uint32_t bar = smem_u32(&mbar);

    if (tid == 0) {
        asm volatile("mbarrier.init.shared.b64 [%0], %1;" :: "r"(bar), "r"(1) : "memory");
    }
    __syncthreads();

    // Thread 0: issue one bulk L2->SMEM copy per in-bounds row (TMA engine path,
    // bypasses L1 + register file entirely).
    if (tid == 0) {
        int n_valid = 0;
        #pragma unroll
        for (int r = 0; r < STAGE_ROWS; r++) {
            int g = g0 + r;
            if (g >= 0 && g < M_DIM) n_valid++;
        }
        asm volatile("mbarrier.arrive.expect_tx.shared.b64 _, [%0], %1;"
                     :: "r"(bar), "r"(n_valid * ROW_BYTES) : "memory");
        #pragma unroll
        for (int r = 0; r < STAGE_ROWS; r++) {
            int g = g0 + r;
            if (g >= 0 && g < M_DIM) {
                uint32_t dst = smem_u32(sm + r * RSTRIDE + LPAD);
                const float* src = img + g * N_DIM;
                asm volatile(
                    "cp.async.bulk.shared::cta.global.mbarrier::complete_tx::bytes "
                    "[%0], [%1], %2, [%3];"
                    :: "r"(dst), "l"(src), "r"(ROW_BYTES), "r"(bar) : "memory");
            }
        }
    }

    // Meanwhile: zero the pads (72 floats/row, disjoint from TMA destinations)
    for (int v = tid; v < STAGE_ROWS * (LPAD + RPAD); v += 256) {
        int r = v / (LPAD + RPAD);
        int p = v % (LPAD + RPAD);
        int idx = (p < LPAD) ? p : (LPAD + N_DIM + (p - LPAD));
        sm[r * RSTRIDE + idx] = 0.0f;
    }
    // ...and zero out-of-bounds rows (only first/last block of each image)
    #pragma unroll
    for (int r = 0; r < STAGE_ROWS; r++) {
        int g = g0 + r;
        if (g < 0 || g >= M_DIM) {
            for (int c = tid; c < N_DIM / 4; c += 256)
                reinterpret_cast<float4*>(sm + r * RSTRIDE + LPAD)[c] =
                    make_float4(0.0f, 0.0f, 0.0f, 0.0f);
        }
    }
    __syncthreads();

    // Wait for the bulk copies (acquire orders subsequent LDS after TMA writes)
    {
        uint32_t done;
        do {
            asm volatile(
                "{\n\t.reg .pred p;\n\t"
                "mbarrier.try_wait.parity.acquire.cta.shared::cta.b64 p, [%1], %2;\n\t"
                "selp.b32 %0, 1, 0, p;\n\t}"
                : "=r"(done) : "r"(bar), "r"(0u) : "memory");
        } while (!done);
    }

    const int   xs    = tid * 4;
    const float xlb   = (float)xs;
    const int   sbase = s * (M_DIM * N_DIM);

    #pragma unroll
    for (int r = 0; r < ROWS_PER_BLK; r++) {
        const int y = ybase + r;

        // Vertical terms (reference formula chain), once per row
        float yl  = 2.0f * (float)y / (float)(M_DIM - 1) - 1.0f;
        float iy  = ((yl + 1.0f) * (float)M_DIM - 1.0f) * 0.5f;
        float y0f = floorf(iy);
        float wy1 = iy - y0f;
        int   r0  = (int)y0f - g0;                 // staged row index, in [0,4]
        const float* __restrict__ rowb = sm + r0 * RSTRIDE;

        float4 dv = *reinterpret_cast<const float4*>(lr + sbase + y * N_DIM + xs);
        float dd[4] = {dv.x, dv.y, dv.z, dv.w};
        float res[4];

        #pragma unroll
        for (int j = 0; j < 4; j++) {
            float d  = dd[j];
            float xr = (xlb + (float)j) - d;

            // Reference expression chain (verified rounding)
            float xr_normed = 2.0f * xr / (float)(N_DIM - 1) - 1.0f;
            float ix = ((xr_normed + 1.0f) * (float)N_DIM - 1.0f) * 0.5f;

            float x0f = floorf(ix);
            float wx1 = ix - x0f;
            int   idx = (int)x0f + LPAD;          // provably in [3, 1092]: pads absorb OOB

            float v00 = rowb[idx];
            float v01 = rowb[idx + 1];
            float v10 = rowb[idx + RSTRIDE];
            float v11 = rowb[idx + RSTRIDE + 1];

            float wx0 = 1.0f - wx1;
            float wy0 = 1.0f - wy1;
            float warped = (v00 * wx0 + v01 * wx1) * wy0
                         + (v10 * wx0 + v11 * wx1) * wy1;

            float dist = fabsf(d + warped);
            bool invalid = (xr < 0.0f) || (xr >= (float)N_DIM);
            res[j] = invalid ? INVALID_VAL : dist;
        }

        *reinterpret_cast<float4*>(out + sbase + y * N_DIM + xs) =
            make_float4(res[0], res[1], res[2], res[3]);
    }
}

extern "C" void kernel_launch(void* const* d_in, const int* in_sizes, int n_in,
                              void* d_out, int out_size)
{
    const float* lr = (const float*)d_in[0];
    const float* rl = (const float*)d_in[1];
    float* out = (float*)d_out;

    int blocks = S_DIM * (M_DIM / ROWS_PER_BLK);   // 3072
    lr_distance_kernel<<<blocks, 256>>>(lr, rl, out);
}